// round 1
// baseline (speedup 1.0000x reference)
#include <cuda_runtime.h>
#include <math.h>

// Problem constants
#define B_   16
#define L_   512
#define H_   1024
#define HS   64     // HEAD_SIZE
#define NH   12     // HEADS
#define INFV 1000000000000.0f

// Scratch (allocation-free rule: __device__ globals)
// q/k stored TRANSPOSED: [b][d][l] so logits_kernel tile loads are coalesced
// and match the d-major smem layout needed for the NT dot product.
__device__ __align__(16) float g_qwT[B_ * HS * L_];          // 2 MB
__device__ __align__(16) float g_kwT[B_ * HS * L_];          // 2 MB
__device__ __align__(16) float g_bias[B_ * 2 * NH * L_];     // 768 KB

// ---------------------------------------------------------------------------
// Kernel A: x = inputs@W1 + b1  (64x128 tile per block, K=1024)
//           -> RoPE(q,k) written transposed, bias = (x@W2 + b2)/2
// grid 128 blocks, 256 threads. Register-prefetch double buffering.
// ---------------------------------------------------------------------------
__global__ __launch_bounds__(256) void proj_kernel(
    const float* __restrict__ inp, const float* __restrict__ W1,
    const float* __restrict__ b1,  const float* __restrict__ W2,
    const float* __restrict__ b2)
{
    __shared__ __align__(16) float As[16][68];    // As[k][m], padded
    __shared__ __align__(16) float Bs[16][132];   // Bs[k][n], padded
    __shared__ __align__(16) float xs[64][132];   // x tile for epilogue

    const int tid = threadIdx.x;
    const int tx  = tid & 31;       // N direction (4 cols each)
    const int ty  = tid >> 5;       // M direction (8 rows each)
    const int m0  = blockIdx.x * 64;

    // global-load assignments
    const int arow   = tid >> 2;    // 0..63
    const int acol4  = tid & 3;     // 0..3 (x4 floats)
    const int brow0  = tid >> 5;    // 0..7
    const int bcol40 = tid & 31;    // 0..31 (x4 floats)

    const float* aptr = inp + (size_t)(m0 + arow) * H_ + acol4 * 4;
    const float* bptr = W1 + (size_t)brow0 * 128 + bcol40 * 4;

    float4 pa  = *(const float4*)aptr;
    float4 pb0 = *(const float4*)bptr;
    float4 pb1 = *(const float4*)(bptr + 8 * 128);

    float acc[8][4];
    #pragma unroll
    for (int r = 0; r < 8; r++)
        #pragma unroll
        for (int c = 0; c < 4; c++) acc[r][c] = 0.f;

    for (int kt = 0; kt < 64; kt++) {
        __syncthreads();
        As[acol4 * 4 + 0][arow] = pa.x;
        As[acol4 * 4 + 1][arow] = pa.y;
        As[acol4 * 4 + 2][arow] = pa.z;
        As[acol4 * 4 + 3][arow] = pa.w;
        *(float4*)&Bs[brow0][bcol40 * 4]     = pb0;
        *(float4*)&Bs[brow0 + 8][bcol40 * 4] = pb1;
        __syncthreads();
        if (kt < 63) {
            pa  = *(const float4*)(aptr + (kt + 1) * 16);
            pb0 = *(const float4*)(bptr + (size_t)(kt + 1) * 16 * 128);
            pb1 = *(const float4*)(bptr + (size_t)(kt + 1) * 16 * 128 + 8 * 128);
        }
        #pragma unroll
        for (int kk = 0; kk < 16; kk++) {
            float4 a0 = *(float4*)&As[kk][ty * 8];
            float4 a1 = *(float4*)&As[kk][ty * 8 + 4];
            float4 bb = *(float4*)&Bs[kk][tx * 4];
            float av[8] = {a0.x, a0.y, a0.z, a0.w, a1.x, a1.y, a1.z, a1.w};
            float bv[4] = {bb.x, bb.y, bb.z, bb.w};
            #pragma unroll
            for (int r = 0; r < 8; r++)
                #pragma unroll
                for (int c = 0; c < 4; c++)
                    acc[r][c] += av[r] * bv[c];
        }
    }

    // ---- epilogue: add b1, stash x tile in smem ----
    float4 b1v = *(const float4*)(b1 + tx * 4);
    float bvv[4] = {b1v.x, b1v.y, b1v.z, b1v.w};
    #pragma unroll
    for (int r = 0; r < 8; r++)
        #pragma unroll
        for (int c = 0; c < 4; c++)
            xs[ty * 8 + r][tx * 4 + c] = acc[r][c] + bvv[c];
    __syncthreads();

    const int bb_ = m0 >> 9;    // batch
    const int l0  = m0 & 511;   // sequence offset of tile

    // ---- RoPE + transposed q/k store ----
    // x layout per row: q[j]=x[2j], k[j]=x[2j+1]; rope pairs (q[2p],q[2p+1])=(x[4p],x[4p+2])
    for (int idx = tid; idx < 2048; idx += 256) {
        int p = idx >> 6;     // 0..31 rope pair
        int i = idx & 63;     // row in tile
        float x0 = xs[i][4 * p + 0];
        float x1 = xs[i][4 * p + 1];
        float x2 = xs[i][4 * p + 2];
        float x3 = xs[i][4 * p + 3];
        // inv_freq = 10000^(-p/32) = 2^(-p/32 * log2(10000))
        float base = exp2f((float)p * -0.41524101186091903f);
        float fr = (float)(l0 + i) * base;
        float s, c;
        sincosf(fr, &s, &c);
        float q0 = x0 * c - x2 * s;
        float q1 = x0 * s + x2 * c;
        float k0 = x1 * c - x3 * s;
        float k1 = x1 * s + x3 * c;
        int d0 = 2 * p;
        g_qwT[(bb_ * HS + d0) * L_ + l0 + i]     = q0;
        g_qwT[(bb_ * HS + d0 + 1) * L_ + l0 + i] = q1;
        g_kwT[(bb_ * HS + d0) * L_ + l0 + i]     = k0;
        g_kwT[(bb_ * HS + d0 + 1) * L_ + l0 + i] = k1;
    }

    // ---- bias = (x@W2 + b2)/2, stored [b][j][l] ----
    if (tid < 192) {
        int jj = tid % 24;
        int r0 = (tid / 24) * 8;
        float accb[8];
        #pragma unroll
        for (int r = 0; r < 8; r++) accb[r] = 0.f;
        for (int cc = 0; cc < 128; cc++) {
            float w = __ldg(&W2[cc * 24 + jj]);
            #pragma unroll
            for (int r = 0; r < 8; r++) accb[r] += xs[r0 + r][cc] * w;
        }
        float bv2 = __ldg(&b2[jj]);
        #pragma unroll
        for (int r = 0; r < 8; r++)
            g_bias[(bb_ * 24 + jj) * L_ + l0 + r0 + r] = (accb[r] + bv2) * 0.5f;
    }
}

// ---------------------------------------------------------------------------
// Kernel B: S = q.k^T/8 on a 64x64 tile, fold mask+tril penalties once,
// then stream 12 heads of S + bias terms. Write-bandwidth bound.
// grid (8 n-tiles, 8 m-tiles, 16 batch), 256 threads (16x16, 4x4 per thread).
// ---------------------------------------------------------------------------
__global__ __launch_bounds__(256) void logits_kernel(
    const float* __restrict__ am, float* __restrict__ out)
{
    __shared__ __align__(16) float Qt[64][68];   // Qt[d][i]  (d-major)
    __shared__ __align__(16) float Kt[64][68];   // Kt[d][j]
    __shared__ float brm[12][64];   // bias[b][2h+1][m0+i]  (varies with m)
    __shared__ float bcn[12][64];   // bias[b][2h  ][n0+j]  (varies with n)
    __shared__ float amm[64], amn[64];

    const int b  = blockIdx.z;
    const int m0 = blockIdx.y * 64;
    const int n0 = blockIdx.x * 64;
    const int tid = threadIdx.x;

    // coalesced tile loads straight into d-major smem
    #pragma unroll
    for (int f = tid; f < 1024; f += 256) {
        int d = f >> 4, ig = f & 15;
        *(float4*)&Qt[d][ig * 4] = *(const float4*)&g_qwT[(b * HS + d) * L_ + m0 + ig * 4];
        *(float4*)&Kt[d][ig * 4] = *(const float4*)&g_kwT[(b * HS + d) * L_ + n0 + ig * 4];
    }
    #pragma unroll
    for (int f = tid; f < 768; f += 256) {
        int h = f >> 6, i = f & 63;
        brm[h][i] = g_bias[(b * 24 + 2 * h + 1) * L_ + m0 + i];
        bcn[h][i] = g_bias[(b * 24 + 2 * h) * L_ + n0 + i];
    }
    if (tid < 64)       amm[tid]      = am[b * L_ + m0 + tid];
    else if (tid < 128) amn[tid - 64] = am[b * L_ + n0 + tid - 64];
    __syncthreads();

    const int tx = tid & 15;   // n direction, 4 cols
    const int ty = tid >> 4;   // m direction, 4 rows

    float acc[4][4];
    #pragma unroll
    for (int r = 0; r < 4; r++)
        #pragma unroll
        for (int c = 0; c < 4; c++) acc[r][c] = 0.f;

    #pragma unroll 16
    for (int d = 0; d < 64; d++) {
        float4 q = *(float4*)&Qt[d][ty * 4];
        float4 k = *(float4*)&Kt[d][tx * 4];
        float qv[4] = {q.x, q.y, q.z, q.w};
        float kv[4] = {k.x, k.y, k.z, k.w};
        #pragma unroll
        for (int r = 0; r < 4; r++)
            #pragma unroll
            for (int c = 0; c < 4; c++)
                acc[r][c] += qv[r] * kv[c];
    }

    // fold scale + attention-mask penalty + strict-lower tril penalty once
    float amr[4], amc[4];
    #pragma unroll
    for (int r = 0; r < 4; r++) amr[r] = amm[ty * 4 + r];
    #pragma unroll
    for (int c = 0; c < 4; c++) amc[c] = amn[tx * 4 + c];
    #pragma unroll
    for (int r = 0; r < 4; r++) {
        int m = m0 + ty * 4 + r;
        #pragma unroll
        for (int c = 0; c < 4; c++) {
            int n = n0 + tx * 4 + c;
            float pen = (1.f - amr[r] * amc[c]) * INFV + ((n < m) ? INFV : 0.f);
            acc[r][c] = acc[r][c] * 0.125f - pen;
        }
    }

    // stream 12 heads: out[b][h][m][n] = S + bias[b,2h,n] + bias[b,2h+1,m]
    const size_t outbase = (size_t)b * NH * L_ * L_ + (size_t)(m0 + ty * 4) * L_ + n0 + tx * 4;
    #pragma unroll
    for (int h = 0; h < NH; h++) {
        float br[4], bc[4];
        #pragma unroll
        for (int r = 0; r < 4; r++) br[r] = brm[h][ty * 4 + r];
        #pragma unroll
        for (int c = 0; c < 4; c++) bc[c] = bcn[h][tx * 4 + c];
        float* op = out + outbase + (size_t)h * L_ * L_;
        #pragma unroll
        for (int r = 0; r < 4; r++) {
            float4 v;
            v.x = acc[r][0] + br[r] + bc[0];
            v.y = acc[r][1] + br[r] + bc[1];
            v.z = acc[r][2] + br[r] + bc[2];
            v.w = acc[r][3] + br[r] + bc[3];
            *(float4*)(op + (size_t)r * L_) = v;
        }
    }
}

// ---------------------------------------------------------------------------
extern "C" void kernel_launch(void* const* d_in, const int* in_sizes, int n_in,
                              void* d_out, int out_size)
{
    const float* inp = (const float*)d_in[0];  // [16,512,1024]
    const float* am  = (const float*)d_in[1];  // [16,512]
    const float* W1  = (const float*)d_in[2];  // [1024,128]
    const float* b1  = (const float*)d_in[3];  // [128]
    const float* W2  = (const float*)d_in[4];  // [128,24]
    const float* b2  = (const float*)d_in[5];  // [24]
    float* out = (float*)d_out;                // [16,12,512,512]

    proj_kernel<<<128, 256>>>(inp, W1, b1, W2, b2);
    dim3 g(8, 8, 16);
    logits_kernel<<<g, 256>>>(am, out);
}